// round 15
// baseline (speedup 1.0000x reference)
#include <cuda_runtime.h>
#include <cstdint>

// Problem constants
#define Bz 8
#define Cz 256
#define Hz 96
#define Wz 96
#define Kz 3
#define TILE 16          // output pixels per block along x
#define NLANES 64        // channel lanes per pixel (each lane = 4 channels, float4)
#define NTHREADS 512     // 8 pixel-groups * 64 lanes; each thread covers 2 pixels

// NHWC scratch for x: [B][H][W][C] floats = 75.5 MB (static device array; no allocation)
__device__ float g_xt[(size_t)Bz * Hz * Wz * Cz];

// ---------------------------------------------------------------------------
// Kernel 1: NCHW -> NHWC transpose of x (per (b,y) row: C x W -> W x C)
// ---------------------------------------------------------------------------
__global__ void nchw_to_nhwc_kernel(const float* __restrict__ x) {
    __shared__ float tile[32][33];
    const int by  = blockIdx.z;           // b*H + y
    const int b   = by / Hz;
    const int y   = by - b * Hz;
    const int wb  = blockIdx.x * 32;      // w tile base
    const int cb  = blockIdx.y * 32;      // c tile base
    const int tx  = threadIdx.x;          // 0..31
    const int ty  = threadIdx.y;          // 0..7

    const float* src = x + (((size_t)b * Cz + cb) * Hz + y) * Wz + wb;
#pragma unroll
    for (int k = 0; k < 4; k++) {
        tile[ty + k * 8][tx] = src[(size_t)(ty + k * 8) * (Hz * Wz) + tx];
    }
    __syncthreads();

    float* dst = g_xt + (((size_t)b * Hz + y) * Wz + wb) * Cz + cb;
#pragma unroll
    for (int k = 0; k < 4; k++) {
        dst[(size_t)(ty + k * 8) * Cz + tx] = tile[tx][ty + k * 8];
    }
}

// ---------------------------------------------------------------------------
// Kernel 2: deformable depthwise-weighted sampling, NHWC gathers -> NCHW out
// ---------------------------------------------------------------------------
struct __align__(16) Coord {
    int   i00, i01, i10, i11;     // clamped pixel indices (y*W + x)
    float w00, w01, w10, w11;     // bilinear weights * validity
};

__global__ __launch_bounds__(NTHREADS, 2)
void deform_kernel(const float* __restrict__ offset,
                   const float* __restrict__ weight,
                   const float* __restrict__ bias,
                   float* __restrict__ out) {
    __shared__ Coord sc[TILE * 9];        // per (pixel, tap) coords: 4.6 KB
    __shared__ float sw[9 * Cz];          // per-channel tap weights [kk][c]: 9 KB
    __shared__ float so[TILE * 260];      // output staging, pitch 260: 16.6 KB

    const int x0  = blockIdx.x * TILE;
    const int y   = blockIdx.y;
    const int b   = blockIdx.z;
    const int tid = threadIdx.x;

    // --- stage per-channel weights as [kk][c] for conflict-free float4 LDS ---
    for (int i = tid; i < 9 * Cz; i += NTHREADS) {
        int kk = i >> 8;
        int c  = i & (Cz - 1);
        sw[i] = weight[c * 9 + kk];
    }

    // --- precompute coordinates (channel-independent, 144 entries) ---
    if (tid < TILE * 9) {
        const int p  = tid / 9;
        const int kk = tid - p * 9;
        const int i  = kk / 3;
        const int j  = kk - i * 3;

        const float offy = offset[(((size_t)b * 18 + 2 * kk    ) * Hz + y) * Wz + x0 + p];
        const float offx = offset[(((size_t)b * 18 + 2 * kk + 1) * Hz + y) * Wz + x0 + p];
        const float py = (float)(y - 1 + i) + offy;          // PAD=1, DIL=1, STRIDE=1
        const float px = (float)(x0 + p - 1 + j) + offx;

        const float fy = floorf(py), fx = floorf(px);
        const float wy = py - fy,    wx = px - fx;
        const int   yi = (int)fy,    xi = (int)fx;

        const bool vy0 = (yi     >= 0) && (yi     < Hz);
        const bool vy1 = (yi + 1 >= 0) && (yi + 1 < Hz);
        const bool vx0 = (xi     >= 0) && (xi     < Wz);
        const bool vx1 = (xi + 1 >= 0) && (xi + 1 < Wz);

        const int y0c = min(max(yi,     0), Hz - 1);
        const int y1c = min(max(yi + 1, 0), Hz - 1);
        const int x0c = min(max(xi,     0), Wz - 1);
        const int x1c = min(max(xi + 1, 0), Wz - 1);

        Coord cd;
        cd.i00 = y0c * Wz + x0c;
        cd.i01 = y0c * Wz + x1c;
        cd.i10 = y1c * Wz + x0c;
        cd.i11 = y1c * Wz + x1c;
        cd.w00 = (1.f - wy) * (1.f - wx) * ((vy0 && vx0) ? 1.f : 0.f);
        cd.w01 = (1.f - wy) * wx         * ((vy0 && vx1) ? 1.f : 0.f);
        cd.w10 = wy         * (1.f - wx) * ((vy1 && vx0) ? 1.f : 0.f);
        cd.w11 = wy         * wx         * ((vy1 && vx1) ? 1.f : 0.f);
        sc[tid] = cd;
    }
    __syncthreads();

    // --- hot loop: warp = one pixel-group, 32 consecutive channel lanes ---
    const int cl = tid & (NLANES - 1);    // channel lane: channels 4cl..4cl+3
    const int pg = tid >> 6;              // pixel group 0..7 (handles pg and pg+8)

    const float4* xt4 = (const float4*)g_xt + (size_t)b * (Hz * Wz * (Cz / 4)) + cl;

    float4 acc0 = make_float4(0.f, 0.f, 0.f, 0.f);
    float4 acc1 = make_float4(0.f, 0.f, 0.f, 0.f);

#pragma unroll
    for (int kk = 0; kk < 9; kk++) {
        const float4 wk = *(const float4*)&sw[kk * Cz + cl * 4];

        {
            const Coord cd = sc[pg * 9 + kk];       // warp-uniform broadcast
            const float4 v00 = xt4[(size_t)cd.i00 * (Cz / 4)];
            const float4 v01 = xt4[(size_t)cd.i01 * (Cz / 4)];
            const float4 v10 = xt4[(size_t)cd.i10 * (Cz / 4)];
            const float4 v11 = xt4[(size_t)cd.i11 * (Cz / 4)];
            float4 s;
            s.x = cd.w00 * v00.x + cd.w01 * v01.x + cd.w10 * v10.x + cd.w11 * v11.x;
            s.y = cd.w00 * v00.y + cd.w01 * v01.y + cd.w10 * v10.y + cd.w11 * v11.y;
            s.z = cd.w00 * v00.z + cd.w01 * v01.z + cd.w10 * v10.z + cd.w11 * v11.z;
            s.w = cd.w00 * v00.w + cd.w01 * v01.w + cd.w10 * v10.w + cd.w11 * v11.w;
            acc0.x += wk.x * s.x; acc0.y += wk.y * s.y;
            acc0.z += wk.z * s.z; acc0.w += wk.w * s.w;
        }
        {
            const Coord cd = sc[(pg + 8) * 9 + kk];
            const float4 v00 = xt4[(size_t)cd.i00 * (Cz / 4)];
            const float4 v01 = xt4[(size_t)cd.i01 * (Cz / 4)];
            const float4 v10 = xt4[(size_t)cd.i10 * (Cz / 4)];
            const float4 v11 = xt4[(size_t)cd.i11 * (Cz / 4)];
            float4 s;
            s.x = cd.w00 * v00.x + cd.w01 * v01.x + cd.w10 * v10.x + cd.w11 * v11.x;
            s.y = cd.w00 * v00.y + cd.w01 * v01.y + cd.w10 * v10.y + cd.w11 * v11.y;
            s.z = cd.w00 * v00.z + cd.w01 * v01.z + cd.w10 * v10.z + cd.w11 * v11.z;
            s.w = cd.w00 * v00.w + cd.w01 * v01.w + cd.w10 * v10.w + cd.w11 * v11.w;
            acc1.x += wk.x * s.x; acc1.y += wk.y * s.y;
            acc1.z += wk.z * s.z; acc1.w += wk.w * s.w;
        }
    }

    // --- bias ---
    const float4 bb = *(const float4*)&bias[cl * 4];
    acc0.x += bb.x; acc0.y += bb.y; acc0.z += bb.z; acc0.w += bb.w;
    acc1.x += bb.x; acc1.y += bb.y; acc1.z += bb.z; acc1.w += bb.w;

    // --- stage to smem (aligned float4 STS, conflict-free), write NCHW coalesced ---
    __syncthreads();   // coords smem no longer needed; order staging after compute
    *(float4*)&so[pg * 260 + cl * 4]       = acc0;
    *(float4*)&so[(pg + 8) * 260 + cl * 4] = acc1;
    __syncthreads();

    // 16 pixels x 256 channels = 4096 elems; 512 threads -> 8 iterations
    float* outb = out + (((size_t)b * Cz) * Hz + y) * Wz + x0;
#pragma unroll
    for (int it = 0; it < 8; it++) {
        const int c = (tid >> 4) + it * 32;   // 32 channels per pass, 0..255
        const int p = tid & 15;
        outb[(size_t)c * (Hz * Wz) + p] = so[p * 260 + c];
    }
}

// ---------------------------------------------------------------------------
// Launch
// ---------------------------------------------------------------------------
extern "C" void kernel_launch(void* const* d_in, const int* in_sizes, int n_in,
                              void* d_out, int out_size) {
    const float* x      = (const float*)d_in[0];   // (B, C, H, W)
    const float* offset = (const float*)d_in[1];   // (B, 18, H, W)
    const float* weight = (const float*)d_in[2];   // (C, 1, 3, 3)
    const float* bias   = (const float*)d_in[3];   // (C,)
    float* out = (float*)d_out;                    // (B, C, H, W)

    (void)in_sizes; (void)n_in; (void)out_size;

    dim3 tgrid(Wz / 32, Cz / 32, Bz * Hz);
    dim3 tblock(32, 8);
    nchw_to_nhwc_kernel<<<tgrid, tblock>>>(x);

    dim3 dgrid(Wz / TILE, Hz, Bz);
    deform_kernel<<<dgrid, NTHREADS>>>(offset, weight, bias, out);
}

// round 16
// speedup vs baseline: 1.2913x; 1.2913x over previous
#include <cuda_runtime.h>
#include <cuda_fp16.h>
#include <cstdint>

// Problem constants
#define Bz 8
#define Cz 256
#define Hz 96
#define Wz 96
#define TILE 16          // output pixels per block along x
#define NTHREADS 256     // 8 warps; warp = 32 lanes x 8 channels, 2 pixels each

// NHWC fp16 scratch for x: [B][H][W][C] halves = 37.7 MB (static; no allocation)
__device__ __half g_xt[(size_t)Bz * Hz * Wz * Cz];

// ---------------------------------------------------------------------------
// Kernel 1: NCHW fp32 -> NHWC fp16 transpose (half2 stores, coalesced)
// ---------------------------------------------------------------------------
__global__ void nchw_to_nhwc_h_kernel(const float* __restrict__ x) {
    __shared__ float tile[64][33];
    const int bz = blockIdx.z;            // b*H + y
    const int b  = bz / Hz;
    const int y  = bz - b * Hz;
    const int wb = blockIdx.x * 32;       // w tile base
    const int cb = blockIdx.y * 64;       // c tile base (64 channels per block)
    const int tx = threadIdx.x;           // 0..31
    const int ty = threadIdx.y;           // 0..15

    const float* src = x + (((size_t)b * Cz + cb) * Hz + y) * Wz + wb;
#pragma unroll
    for (int k = 0; k < 4; k++) {
        const int c = ty + k * 16;
        tile[c][tx] = src[(size_t)c * (Hz * Wz) + tx];
    }
    __syncthreads();

    __half2* dst = (__half2*)g_xt;
#pragma unroll
    for (int r = 0; r < 2; r++) {
        const int w = ty * 2 + r;
        const __half2 h = __floats2half2_rn(tile[2 * tx][w], tile[2 * tx + 1][w]);
        dst[((((size_t)(b * Hz + y)) * Wz + wb + w) * Cz + cb) / 2 + tx] = h;
    }
}

// ---------------------------------------------------------------------------
// Kernel 2: deformable depthwise-weighted sampling, fp16 NHWC gathers,
//           fp32 math, NCHW coalesced output
// ---------------------------------------------------------------------------
struct __align__(16) Coord {
    int   i00, i01, i10, i11;     // clamped pixel indices (y*W + x)
    float w00, w01, w10, w11;     // bilinear weights * validity (fp32)
};

// Combine one half2 slot (2 channels) across 4 corners in fp32, accumulate.
#define CORNER2(u00, u01, u10, u11, wlo, whi, accr) {                          \
    const float2 f00 = __half22float2(*reinterpret_cast<const __half2*>(&(u00))); \
    const float2 f01 = __half22float2(*reinterpret_cast<const __half2*>(&(u01))); \
    const float2 f10 = __half22float2(*reinterpret_cast<const __half2*>(&(u10))); \
    const float2 f11 = __half22float2(*reinterpret_cast<const __half2*>(&(u11))); \
    const float sx = cd.w00 * f00.x + cd.w01 * f01.x + cd.w10 * f10.x + cd.w11 * f11.x; \
    const float sy = cd.w00 * f00.y + cd.w01 * f01.y + cd.w10 * f10.y + cd.w11 * f11.y; \
    (accr).x = fmaf((wlo), sx, (accr).x);                                      \
    (accr).y = fmaf((whi), sy, (accr).y); }

__global__ __launch_bounds__(NTHREADS, 3)
void deform_kernel(const float* __restrict__ offset,
                   const float* __restrict__ weight,
                   const float* __restrict__ bias,
                   float* __restrict__ out) {
    __shared__ Coord sc[TILE * 9];        // per (pixel, tap) coords: 4.6 KB
    __shared__ float sw[9 * Cz];          // per-channel tap weights [kk][c]: 9 KB
    __shared__ float so[TILE * 260];      // output staging, pitch 260: 16.6 KB

    const int x0  = blockIdx.x * TILE;
    const int y   = blockIdx.y;
    const int b   = blockIdx.z;
    const int tid = threadIdx.x;

    // --- stage per-channel weights as [kk][c] ---
    for (int i = tid; i < 9 * Cz; i += NTHREADS) {
        const int kk = i >> 8;
        const int c  = i & (Cz - 1);
        sw[i] = weight[c * 9 + kk];
    }

    // --- precompute coordinates (channel-independent, 144 entries) ---
    if (tid < TILE * 9) {
        const int p  = tid / 9;
        const int kk = tid - p * 9;
        const int i  = kk / 3;
        const int j  = kk - i * 3;

        const float offy = offset[(((size_t)b * 18 + 2 * kk    ) * Hz + y) * Wz + x0 + p];
        const float offx = offset[(((size_t)b * 18 + 2 * kk + 1) * Hz + y) * Wz + x0 + p];
        const float py = (float)(y - 1 + i) + offy;          // PAD=1, DIL=1, STRIDE=1
        const float px = (float)(x0 + p - 1 + j) + offx;

        const float fy = floorf(py), fx = floorf(px);
        const float wy = py - fy,    wx = px - fx;
        const int   yi = (int)fy,    xi = (int)fx;

        const bool vy0 = (yi     >= 0) && (yi     < Hz);
        const bool vy1 = (yi + 1 >= 0) && (yi + 1 < Hz);
        const bool vx0 = (xi     >= 0) && (xi     < Wz);
        const bool vx1 = (xi + 1 >= 0) && (xi + 1 < Wz);

        const int y0c = min(max(yi,     0), Hz - 1);
        const int y1c = min(max(yi + 1, 0), Hz - 1);
        const int x0c = min(max(xi,     0), Wz - 1);
        const int x1c = min(max(xi + 1, 0), Wz - 1);

        Coord cd;
        cd.i00 = y0c * Wz + x0c;
        cd.i01 = y0c * Wz + x1c;
        cd.i10 = y1c * Wz + x0c;
        cd.i11 = y1c * Wz + x1c;
        cd.w00 = (1.f - wy) * (1.f - wx) * ((vy0 && vx0) ? 1.f : 0.f);
        cd.w01 = (1.f - wy) * wx         * ((vy0 && vx1) ? 1.f : 0.f);
        cd.w10 = wy         * (1.f - wx) * ((vy1 && vx0) ? 1.f : 0.f);
        cd.w11 = wy         * wx         * ((vy1 && vx1) ? 1.f : 0.f);
        sc[tid] = cd;
    }
    __syncthreads();

    // --- hot loop: warp = 32 lanes x 8 channels, 2 pixels per warp ---
    const int lane = tid & 31;            // channels 8*lane .. 8*lane+7
    const int wrp  = tid >> 5;            // 0..7
    const int p0   = wrp * 2;             // pixels p0, p0+1

    // uint4 = 8 halves = 8 channels; row pitch = Cz halves = 32 uint4
    const uint4* xb = ((const uint4*)g_xt) + (size_t)b * (Hz * Wz * 32) + lane;

    float2 acc[2][4];
#pragma unroll
    for (int p = 0; p < 2; p++)
#pragma unroll
        for (int j = 0; j < 4; j++) acc[p][j] = make_float2(0.f, 0.f);

#pragma unroll
    for (int kk = 0; kk < 9; kk++) {
        const float4 wkA = *(const float4*)&sw[kk * Cz + lane * 8];
        const float4 wkB = *(const float4*)&sw[kk * Cz + lane * 8 + 4];
#pragma unroll
        for (int p = 0; p < 2; p++) {
            const Coord cd = sc[(p0 + p) * 9 + kk];     // warp-uniform broadcast
            const uint4 q00 = xb[(size_t)cd.i00 * 32];
            const uint4 q01 = xb[(size_t)cd.i01 * 32];
            const uint4 q10 = xb[(size_t)cd.i10 * 32];
            const uint4 q11 = xb[(size_t)cd.i11 * 32];
            CORNER2(q00.x, q01.x, q10.x, q11.x, wkA.x, wkA.y, acc[p][0]);
            CORNER2(q00.y, q01.y, q10.y, q11.y, wkA.z, wkA.w, acc[p][1]);
            CORNER2(q00.z, q01.z, q10.z, q11.z, wkB.x, wkB.y, acc[p][2]);
            CORNER2(q00.w, q01.w, q10.w, q11.w, wkB.z, wkB.w, acc[p][3]);
        }
    }

    // --- bias + stage to smem, then coalesced NCHW write ---
    const float4 b0 = *(const float4*)&bias[lane * 8];
    const float4 b1 = *(const float4*)&bias[lane * 8 + 4];

    __syncthreads();   // sc no longer needed; order before so-staging
#pragma unroll
    for (int p = 0; p < 2; p++) {
        const float4 o0 = make_float4(acc[p][0].x + b0.x, acc[p][0].y + b0.y,
                                      acc[p][1].x + b0.z, acc[p][1].y + b0.w);
        const float4 o1 = make_float4(acc[p][2].x + b1.x, acc[p][2].y + b1.y,
                                      acc[p][3].x + b1.z, acc[p][3].y + b1.w);
        *(float4*)&so[(p0 + p) * 260 + lane * 8]     = o0;
        *(float4*)&so[(p0 + p) * 260 + lane * 8 + 4] = o1;
    }
    __syncthreads();

    // 16 pixels x 256 channels = 4096 elems; 256 threads -> 16 iterations
    float* outb = out + (((size_t)b * Cz) * Hz + y) * Wz + x0;
#pragma unroll
    for (int it = 0; it < 16; it++) {
        const int c = (tid >> 4) + it * 16;
        const int p = tid & 15;
        outb[(size_t)c * (Hz * Wz) + p] = so[p * 260 + c];
    }
}

// ---------------------------------------------------------------------------
// Launch
// ---------------------------------------------------------------------------
extern "C" void kernel_launch(void* const* d_in, const int* in_sizes, int n_in,
                              void* d_out, int out_size) {
    const float* x      = (const float*)d_in[0];   // (B, C, H, W)
    const float* offset = (const float*)d_in[1];   // (B, 18, H, W)
    const float* weight = (const float*)d_in[2];   // (C, 1, 3, 3)
    const float* bias   = (const float*)d_in[3];   // (C,)
    float* out = (float*)d_out;                    // (B, C, H, W)

    (void)in_sizes; (void)n_in; (void)out_size;

    dim3 tgrid(Wz / 32, Cz / 64, Bz * Hz);
    dim3 tblock(32, 16);
    nchw_to_nhwc_h_kernel<<<tgrid, tblock>>>(x);

    dim3 dgrid(Wz / TILE, Hz, Bz);
    deform_kernel<<<dgrid, NTHREADS>>>(offset, weight, bias, out);
}

// round 17
// speedup vs baseline: 1.3016x; 1.0080x over previous
#include <cuda_runtime.h>
#include <cuda_fp16.h>
#include <cstdint>

// Problem constants
#define Bz 8
#define Cz 256
#define Hz 96
#define Wz 96
#define TILE 16          // output pixels per block along x
#define NTHREADS 256     // 8 warps; warp = 32 lanes x 8 channels, 2 pixels each

// NHWC fp16 scratch for x: [B][H][W][C] halves = 37.7 MB (static; no allocation)
__device__ __half g_xt[(size_t)Bz * Hz * Wz * Cz];

// ---------------------------------------------------------------------------
// Kernel 1: NCHW fp32 -> NHWC fp16 transpose (half2 stores, coalesced)
// ---------------------------------------------------------------------------
__global__ void nchw_to_nhwc_h_kernel(const float* __restrict__ x) {
    __shared__ float tile[64][33];
    const int bz = blockIdx.z;            // b*H + y
    const int b  = bz / Hz;
    const int y  = bz - b * Hz;
    const int wb = blockIdx.x * 32;       // w tile base
    const int cb = blockIdx.y * 64;       // c tile base (64 channels per block)
    const int tx = threadIdx.x;           // 0..31
    const int ty = threadIdx.y;           // 0..15

    const float* src = x + (((size_t)b * Cz + cb) * Hz + y) * Wz + wb;
#pragma unroll
    for (int k = 0; k < 4; k++) {
        const int c = ty + k * 16;
        tile[c][tx] = src[(size_t)c * (Hz * Wz) + tx];
    }
    __syncthreads();

    __half2* dst = (__half2*)g_xt;
#pragma unroll
    for (int r = 0; r < 2; r++) {
        const int w = ty * 2 + r;
        const __half2 h = __floats2half2_rn(tile[2 * tx][w], tile[2 * tx + 1][w]);
        dst[((((size_t)(b * Hz + y)) * Wz + wb + w) * Cz + cb) / 2 + tx] = h;
    }
}

// ---------------------------------------------------------------------------
// Kernel 2: deformable depthwise-weighted sampling, fp16 NHWC gathers,
//           fp32 math, NCHW coalesced output
// ---------------------------------------------------------------------------
struct __align__(16) Coord {
    int   i00, i01, i10, i11;     // clamped pixel indices (y*W + x)
    float w00, w01, w10, w11;     // bilinear weights * validity (fp32)
};

// Combine one half2 slot (2 channels) across 4 corners in fp32, accumulate.
#define CORNER2(u00, u01, u10, u11, wlo, whi, accr) {                          \
    const float2 f00 = __half22float2(*reinterpret_cast<const __half2*>(&(u00))); \
    const float2 f01 = __half22float2(*reinterpret_cast<const __half2*>(&(u01))); \
    const float2 f10 = __half22float2(*reinterpret_cast<const __half2*>(&(u10))); \
    const float2 f11 = __half22float2(*reinterpret_cast<const __half2*>(&(u11))); \
    const float sx = cd.w00 * f00.x + cd.w01 * f01.x + cd.w10 * f10.x + cd.w11 * f11.x; \
    const float sy = cd.w00 * f00.y + cd.w01 * f01.y + cd.w10 * f10.y + cd.w11 * f11.y; \
    (accr).x = fmaf((wlo), sx, (accr).x);                                      \
    (accr).y = fmaf((whi), sy, (accr).y); }

__global__ __launch_bounds__(NTHREADS, 3)
void deform_kernel(const float* __restrict__ offset,
                   const float* __restrict__ weight,
                   const float* __restrict__ bias,
                   float* __restrict__ out) {
    __shared__ Coord sc[TILE * 9];        // per (pixel, tap) coords: 4.6 KB
    __shared__ float sw[9 * Cz];          // per-channel tap weights [kk][c]: 9 KB
    __shared__ float so[TILE * 260];      // output staging, pitch 260: 16.6 KB

    const int x0  = blockIdx.x * TILE;
    const int y   = blockIdx.y;
    const int b   = blockIdx.z;
    const int tid = threadIdx.x;

    // --- stage per-channel weights as [kk][c] ---
    for (int i = tid; i < 9 * Cz; i += NTHREADS) {
        const int kk = i >> 8;
        const int c  = i & (Cz - 1);
        sw[i] = weight[c * 9 + kk];
    }

    // --- precompute coordinates (channel-independent, 144 entries) ---
    if (tid < TILE * 9) {
        const int p  = tid / 9;
        const int kk = tid - p * 9;
        const int i  = kk / 3;
        const int j  = kk - i * 3;

        const float offy = offset[(((size_t)b * 18 + 2 * kk    ) * Hz + y) * Wz + x0 + p];
        const float offx = offset[(((size_t)b * 18 + 2 * kk + 1) * Hz + y) * Wz + x0 + p];
        const float py = (float)(y - 1 + i) + offy;          // PAD=1, DIL=1, STRIDE=1
        const float px = (float)(x0 + p - 1 + j) + offx;

        const float fy = floorf(py), fx = floorf(px);
        const float wy = py - fy,    wx = px - fx;
        const int   yi = (int)fy,    xi = (int)fx;

        const bool vy0 = (yi     >= 0) && (yi     < Hz);
        const bool vy1 = (yi + 1 >= 0) && (yi + 1 < Hz);
        const bool vx0 = (xi     >= 0) && (xi     < Wz);
        const bool vx1 = (xi + 1 >= 0) && (xi + 1 < Wz);

        const int y0c = min(max(yi,     0), Hz - 1);
        const int y1c = min(max(yi + 1, 0), Hz - 1);
        const int x0c = min(max(xi,     0), Wz - 1);
        const int x1c = min(max(xi + 1, 0), Wz - 1);

        Coord cd;
        cd.i00 = y0c * Wz + x0c;
        cd.i01 = y0c * Wz + x1c;
        cd.i10 = y1c * Wz + x0c;
        cd.i11 = y1c * Wz + x1c;
        cd.w00 = (1.f - wy) * (1.f - wx) * ((vy0 && vx0) ? 1.f : 0.f);
        cd.w01 = (1.f - wy) * wx         * ((vy0 && vx1) ? 1.f : 0.f);
        cd.w10 = wy         * (1.f - wx) * ((vy1 && vx0) ? 1.f : 0.f);
        cd.w11 = wy         * wx         * ((vy1 && vx1) ? 1.f : 0.f);
        sc[tid] = cd;
    }
    __syncthreads();

    // --- hot loop: warp = 32 lanes x 8 channels, 2 pixels per warp ---
    const int lane = tid & 31;            // channels 8*lane .. 8*lane+7
    const int wrp  = tid >> 5;            // 0..7
    const int p0   = wrp * 2;             // pixels p0, p0+1

    // uint4 = 8 halves = 8 channels; row pitch = Cz halves = 32 uint4
    const uint4* xb = ((const uint4*)g_xt) + (size_t)b * (Hz * Wz * 32) + lane;

    float2 acc[2][4];
#pragma unroll
    for (int p = 0; p < 2; p++)
#pragma unroll
        for (int j = 0; j < 4; j++) acc[p][j] = make_float2(0.f, 0.f);

#pragma unroll
    for (int kk = 0; kk < 9; kk++) {
        const float4 wkA = *(const float4*)&sw[kk * Cz + lane * 8];
        const float4 wkB = *(const float4*)&sw[kk * Cz + lane * 8 + 4];
#pragma unroll
        for (int p = 0; p < 2; p++) {
            const Coord cd = sc[(p0 + p) * 9 + kk];     // warp-uniform broadcast
            const uint4 q00 = xb[(size_t)cd.i00 * 32];
            const uint4 q01 = xb[(size_t)cd.i01 * 32];
            const uint4 q10 = xb[(size_t)cd.i10 * 32];
            const uint4 q11 = xb[(size_t)cd.i11 * 32];
            CORNER2(q00.x, q01.x, q10.x, q11.x, wkA.x, wkA.y, acc[p][0]);
            CORNER2(q00.y, q01.y, q10.y, q11.y, wkA.z, wkA.w, acc[p][1]);
            CORNER2(q00.z, q01.z, q10.z, q11.z, wkB.x, wkB.y, acc[p][2]);
            CORNER2(q00.w, q01.w, q10.w, q11.w, wkB.z, wkB.w, acc[p][3]);
        }
    }

    // --- bias + stage to smem, then coalesced NCHW write ---
    const float4 b0 = *(const float4*)&bias[lane * 8];
    const float4 b1 = *(const float4*)&bias[lane * 8 + 4];

    __syncthreads();   // sc no longer needed; order before so-staging
#pragma unroll
    for (int p = 0; p < 2; p++) {
        const float4 o0 = make_float4(acc[p][0].x + b0.x, acc[p][0].y + b0.y,
                                      acc[p][1].x + b0.z, acc[p][1].y + b0.w);
        const float4 o1 = make_float4(acc[p][2].x + b1.x, acc[p][2].y + b1.y,
                                      acc[p][3].x + b1.z, acc[p][3].y + b1.w);
        *(float4*)&so[(p0 + p) * 260 + lane * 8]     = o0;
        *(float4*)&so[(p0 + p) * 260 + lane * 8 + 4] = o1;
    }
    __syncthreads();

    // 16 pixels x 256 channels = 4096 elems; 256 threads -> 16 iterations
    float* outb = out + (((size_t)b * Cz) * Hz + y) * Wz + x0;
#pragma unroll
    for (int it = 0; it < 16; it++) {
        const int c = (tid >> 4) + it * 16;
        const int p = tid & 15;
        outb[(size_t)c * (Hz * Wz) + p] = so[p * 260 + c];
    }
}

// ---------------------------------------------------------------------------
// Launch
// ---------------------------------------------------------------------------
extern "C" void kernel_launch(void* const* d_in, const int* in_sizes, int n_in,
                              void* d_out, int out_size) {
    const float* x      = (const float*)d_in[0];   // (B, C, H, W)
    const float* offset = (const float*)d_in[1];   // (B, 18, H, W)
    const float* weight = (const float*)d_in[2];   // (C, 1, 3, 3)
    const float* bias   = (const float*)d_in[3];   // (C,)
    float* out = (float*)d_out;                    // (B, C, H, W)

    (void)in_sizes; (void)n_in; (void)out_size;

    dim3 tgrid(Wz / 32, Cz / 64, Bz * Hz);
    dim3 tblock(32, 16);
    nchw_to_nhwc_h_kernel<<<tgrid, tblock>>>(x);

    dim3 dgrid(Wz / TILE, Hz, Bz);
    deform_kernel<<<dgrid, NTHREADS>>>(offset, weight, bias, out);
}